// round 12
// baseline (speedup 1.0000x reference)
#include <cuda_runtime.h>
#include <cuda_bf16.h>
#include <math.h>
#include <stdint.h>

// ---------------- problem dims ----------------
#define NB 8
#define TT 2048
#define DD 1024
#define HH 1536
#define GG 3072              // 2*H
#define MM (NB*TT)           // 16384
#define NCHUNK 16
#define CLEN (TT/NCHUNK)     // 128

// ---------------- scratch ----------------
__device__ float g_u[(size_t)MM*GG];        // u = x @ W_in^T  (gate | xh)
__device__ float g_xc[(size_t)MM*HH];       // conv output fp32
__device__ float g_gp[(size_t)MM*GG];       // gates GEMM out, permuted pairs (forget,inp)
__device__ float2 g_axs[(size_t)MM*HH];     // interleaved (alpha, xs)
__device__ float g_sp[HH];                  // softplus(forget_base)
__device__ float g_carryA[NB*NCHUNK*HH];
__device__ float g_carryH[NB*NCHUNK*HH];
__device__ float g_chunkIn[NB*NCHUNK*HH];
// split-bf16 operand buffers
__device__ __nv_bfloat16 g_ahi[(size_t)MM*HH];
__device__ __nv_bfloat16 g_alo[(size_t)MM*HH];
__device__ __nv_bfloat16 g_bhi[(size_t)GG*HH];
__device__ __nv_bfloat16 g_blo[(size_t)GG*HH];

// ---------------- PTX helpers ----------------
__device__ __forceinline__ uint32_t smem_u32(const void* p) {
    uint32_t a;
    asm("{ .reg .u64 t; cvta.to.shared.u64 t, %1; cvt.u32.u64 %0, t; }" : "=r"(a) : "l"(p));
    return a;
}
__device__ __forceinline__ void ldsm_x4(uint32_t& r0, uint32_t& r1, uint32_t& r2, uint32_t& r3,
                                        uint32_t addr) {
    asm volatile("ldmatrix.sync.aligned.m8n8.x4.shared.b16 {%0,%1,%2,%3}, [%4];"
                 : "=r"(r0), "=r"(r1), "=r"(r2), "=r"(r3) : "r"(addr));
}
__device__ __forceinline__ void mma16816(float* c,
                                         uint32_t a0, uint32_t a1, uint32_t a2, uint32_t a3,
                                         uint32_t b0, uint32_t b1) {
    asm volatile(
        "mma.sync.aligned.m16n8k16.row.col.f32.bf16.bf16.f32 "
        "{%0,%1,%2,%3}, {%4,%5,%6,%7}, {%8,%9}, {%0,%1,%2,%3};"
        : "+f"(c[0]), "+f"(c[1]), "+f"(c[2]), "+f"(c[3])
        : "r"(a0), "r"(a1), "r"(a2), "r"(a3), "r"(b0), "r"(b1));
}

// ---------------- split-bf16 TN GEMM, fused 3-term, single K pass ----------------
// C[M,N] = Ahi*Bhi^T + Ahi*Blo^T + Alo*Bhi^T (+bias done downstream)
// block 128x128, BK=16, 256 threads = 8 warps (2 M x 4 N), warp tile 64x32
// per chunk: stage 4 tiles (Ahi,Alo,Bhi,Blo); ldsm B once, A-buffer reused hi->lo
#define BM 128
#define BN 128
#define BK 16
#define SSTR 24                 // smem row stride in bf16 (16 + 8 pad) — ldsm conflict-free
#define TILE (BM*SSTR)          // bf16 elems per tile (BM==BN)

__device__ __forceinline__ void tn_gemm_body(
    const __nv_bfloat16* __restrict__ Ahi, const __nv_bfloat16* __restrict__ Alo,
    const __nv_bfloat16* __restrict__ Bhi, const __nv_bfloat16* __restrict__ Blo,
    float* __restrict__ C, int Ndim, int Kdim)
{
    __shared__ __align__(16) __nv_bfloat16 smem_s[2 * 4 * TILE];   // 49152 bytes

    const int tid = threadIdx.x;
    const int wid = tid >> 5;
    const int lane = tid & 31;
    const int warp_m = wid >> 2;       // 0..1
    const int warp_n = wid & 3;        // 0..3
    const int m0 = blockIdx.y * BM;
    const int n0 = blockIdx.x * BN;

    // loader mapping: each tile is 128 rows x 16 bf16 = 256 uint4; 256 threads
    const int lrow = tid >> 1;          // 0..127
    const int lhalf = (tid & 1) * 8;    // bf16 offset 0 or 8
    const uint32_t smem_base = smem_u32(smem_s);

    float acc[4][4][4];
#pragma unroll
    for (int i = 0; i < 4; i++)
#pragma unroll
        for (int j = 0; j < 4; j++)
#pragma unroll
            for (int v = 0; v < 4; v++) acc[i][j][v] = 0.f;

    const int nch = Kdim / BK;

    const __nv_bfloat16* srcA_hi = Ahi + (size_t)(m0 + lrow) * Kdim + lhalf;
    const __nv_bfloat16* srcA_lo = Alo + (size_t)(m0 + lrow) * Kdim + lhalf;
    const __nv_bfloat16* srcB_hi = Bhi + (size_t)(n0 + lrow) * Kdim + lhalf;
    const __nv_bfloat16* srcB_lo = Blo + (size_t)(n0 + lrow) * Kdim + lhalf;

    uint4 ra[4];
    auto fetch = [&](int ch) {
        const int k0 = ch * BK;
        ra[0] = *(const uint4*)(srcA_hi + k0);
        ra[1] = *(const uint4*)(srcA_lo + k0);
        ra[2] = *(const uint4*)(srcB_hi + k0);
        ra[3] = *(const uint4*)(srcB_lo + k0);
    };
    auto stage = [&](int s) {
        __nv_bfloat16* base = smem_s + s * 4 * TILE + lrow * SSTR + lhalf;
#pragma unroll
        for (int t = 0; t < 4; t++)
            *(uint4*)(base + t * TILE) = ra[t];
    };

    fetch(0);
    stage(0);
    __syncthreads();

    // fragment address offsets (bytes) within a tile
    const uint32_t a_off[4] = {
        (uint32_t)(((warp_m * 64 +  0 + (lane & 15)) * SSTR + (lane >> 4) * 8) * 2),
        (uint32_t)(((warp_m * 64 + 16 + (lane & 15)) * SSTR + (lane >> 4) * 8) * 2),
        (uint32_t)(((warp_m * 64 + 32 + (lane & 15)) * SSTR + (lane >> 4) * 8) * 2),
        (uint32_t)(((warp_m * 64 + 48 + (lane & 15)) * SSTR + (lane >> 4) * 8) * 2)
    };
    const uint32_t b_off[2] = {
        (uint32_t)(((warp_n * 32 +  0 + (lane & 15)) * SSTR + (lane >> 4) * 8) * 2),
        (uint32_t)(((warp_n * 32 + 16 + (lane & 15)) * SSTR + (lane >> 4) * 8) * 2)
    };

    for (int ch = 0; ch < nch; ch++) {
        const int cur = ch & 1;
        const bool more = (ch + 1 < nch);
        if (more) fetch(ch + 1);

        const uint32_t sAhi = smem_base + (uint32_t)(cur * 4 + 0) * (TILE * 2);
        const uint32_t sAlo = smem_base + (uint32_t)(cur * 4 + 1) * (TILE * 2);
        const uint32_t sBhi = smem_base + (uint32_t)(cur * 4 + 2) * (TILE * 2);
        const uint32_t sBlo = smem_base + (uint32_t)(cur * 4 + 3) * (TILE * 2);

        uint32_t bh[2][4], bl[2][4];
#pragma unroll
        for (int nb = 0; nb < 2; nb++)
            ldsm_x4(bh[nb][0], bh[nb][1], bh[nb][2], bh[nb][3], sBhi + b_off[nb]);
#pragma unroll
        for (int nb = 0; nb < 2; nb++)
            ldsm_x4(bl[nb][0], bl[nb][1], bl[nb][2], bl[nb][3], sBlo + b_off[nb]);

        uint32_t a[4][4];
#pragma unroll
        for (int mi = 0; mi < 4; mi++)
            ldsm_x4(a[mi][0], a[mi][1], a[mi][2], a[mi][3], sAhi + a_off[mi]);
        // Ahi * Bhi  and  Ahi * Blo
#pragma unroll
        for (int mi = 0; mi < 4; mi++) {
#pragma unroll
            for (int nb = 0; nb < 2; nb++) {
                mma16816(acc[mi][nb * 2 + 0], a[mi][0], a[mi][1], a[mi][2], a[mi][3],
                         bh[nb][0], bh[nb][2]);
                mma16816(acc[mi][nb * 2 + 1], a[mi][0], a[mi][1], a[mi][2], a[mi][3],
                         bh[nb][1], bh[nb][3]);
                mma16816(acc[mi][nb * 2 + 0], a[mi][0], a[mi][1], a[mi][2], a[mi][3],
                         bl[nb][0], bl[nb][2]);
                mma16816(acc[mi][nb * 2 + 1], a[mi][0], a[mi][1], a[mi][2], a[mi][3],
                         bl[nb][1], bl[nb][3]);
            }
        }
        // Alo * Bhi   (reuse A fragment registers)
#pragma unroll
        for (int mi = 0; mi < 4; mi++)
            ldsm_x4(a[mi][0], a[mi][1], a[mi][2], a[mi][3], sAlo + a_off[mi]);
#pragma unroll
        for (int mi = 0; mi < 4; mi++) {
#pragma unroll
            for (int nb = 0; nb < 2; nb++) {
                mma16816(acc[mi][nb * 2 + 0], a[mi][0], a[mi][1], a[mi][2], a[mi][3],
                         bh[nb][0], bh[nb][2]);
                mma16816(acc[mi][nb * 2 + 1], a[mi][0], a[mi][1], a[mi][2], a[mi][3],
                         bh[nb][1], bh[nb][3]);
            }
        }

        if (more) {
            stage(cur ^ 1);
            __syncthreads();
        }
    }

    // ---- epilogue: plain coalesced store ----
    const int crow0 = m0 + warp_m * 64 + (lane >> 2);
    const int ccol0 = n0 + warp_n * 32 + (lane & 3) * 2;
#pragma unroll
    for (int mi = 0; mi < 4; mi++) {
#pragma unroll
        for (int ni = 0; ni < 4; ni++) {
            int row = crow0 + mi * 16;
            int col = ccol0 + ni * 8;
            float2 v0, v1;
            v0.x = acc[mi][ni][0]; v0.y = acc[mi][ni][1];
            v1.x = acc[mi][ni][2]; v1.y = acc[mi][ni][3];
            *(float2*)(C + (size_t)row * Ndim + col)       = v0;
            *(float2*)(C + (size_t)(row + 8) * Ndim + col) = v1;
        }
    }
}

__global__ __launch_bounds__(256, 2) void tcgemm_in()
{
    tn_gemm_body(g_ahi, g_alo, g_bhi, g_blo, g_u, GG, DD);
}
__global__ __launch_bounds__(256, 2) void tcgemm_gates()
{
    tn_gemm_body(g_ahi, g_alo, g_bhi, g_blo, g_gp, GG, HH);
}
__global__ __launch_bounds__(256, 2) void tcgemm_out(float* __restrict__ out)
{
    tn_gemm_body(g_ahi, g_alo, g_bhi, g_blo, out, DD, HH);
}

// ---------------- fp32 -> (hi, lo) bf16 split ----------------
__device__ __forceinline__ void split1(float v, __nv_bfloat16& hi, __nv_bfloat16& lo) {
    __nv_bfloat16 h = __float2bfloat16(v);
    hi = h;
    lo = __float2bfloat16(v - __bfloat162float(h));
}
__global__ __launch_bounds__(256) void split_x(const float* __restrict__ x, int n4)
{
    int id = blockIdx.x * blockDim.x + threadIdx.x;
    if (id >= n4) return;
    float4 v = ((const float4*)x)[id];
    __nv_bfloat16 h0, h1, h2, h3, l0, l1, l2, l3;
    split1(v.x, h0, l0); split1(v.y, h1, l1);
    split1(v.z, h2, l2); split1(v.w, h3, l3);
    ((__nv_bfloat162*)g_ahi)[id * 2 + 0] = __nv_bfloat162(h0, h1);
    ((__nv_bfloat162*)g_ahi)[id * 2 + 1] = __nv_bfloat162(h2, h3);
    ((__nv_bfloat162*)g_alo)[id * 2 + 0] = __nv_bfloat162(l0, l1);
    ((__nv_bfloat162*)g_alo)[id * 2 + 1] = __nv_bfloat162(l2, l3);
}
__global__ __launch_bounds__(256) void split_w(const float* __restrict__ w, int n4)
{
    int id = blockIdx.x * blockDim.x + threadIdx.x;
    if (id >= n4) return;
    float4 v = ((const float4*)w)[id];
    __nv_bfloat16 h0, h1, h2, h3, l0, l1, l2, l3;
    split1(v.x, h0, l0); split1(v.y, h1, l1);
    split1(v.z, h2, l2); split1(v.w, h3, l3);
    ((__nv_bfloat162*)g_bhi)[id * 2 + 0] = __nv_bfloat162(h0, h1);
    ((__nv_bfloat162*)g_bhi)[id * 2 + 1] = __nv_bfloat162(h2, h3);
    ((__nv_bfloat162*)g_blo)[id * 2 + 0] = __nv_bfloat162(l0, l1);
    ((__nv_bfloat162*)g_blo)[id * 2 + 1] = __nv_bfloat162(l2, l3);
}
// permuted split for W_gates: dst row 2h = W_gates row h (forget), 2h+1 = row HH+h (inp)
__global__ __launch_bounds__(256) void split_w_gates(const float* __restrict__ w, int n4)
{
    int id = blockIdx.x * blockDim.x + threadIdx.x;
    if (id >= n4) return;
    int e = id * 4;
    int j = e / HH;                    // dst row
    int o = e - j * HH;
    int src = (j & 1) ? (HH + (j >> 1)) : (j >> 1);
    float4 v = *(const float4*)(w + (size_t)src * HH + o);
    __nv_bfloat16 h0, h1, h2, h3, l0, l1, l2, l3;
    split1(v.x, h0, l0); split1(v.y, h1, l1);
    split1(v.z, h2, l2); split1(v.w, h3, l3);
    ((__nv_bfloat162*)g_bhi)[id * 2 + 0] = __nv_bfloat162(h0, h1);
    ((__nv_bfloat162*)g_bhi)[id * 2 + 1] = __nv_bfloat162(h2, h3);
    ((__nv_bfloat162*)g_blo)[id * 2 + 0] = __nv_bfloat162(l0, l1);
    ((__nv_bfloat162*)g_blo)[id * 2 + 1] = __nv_bfloat162(l2, l3);
}
__global__ __launch_bounds__(256) void prep_sp(const float* __restrict__ fb)
{
    int i = blockIdx.x * blockDim.x + threadIdx.x;
    if (i < HH) g_sp[i] = log1pf(expf(fb[i]));
}

// ---------------- causal depthwise conv, fused with split ----------------
__global__ __launch_bounds__(256) void conv_kernel(
    const float* __restrict__ cw, const float* __restrict__ cb)
{
    int id = blockIdx.x * blockDim.x + threadIdx.x;
    if (id >= MM * HH) return;
    int h = id % HH;
    int m = id / HH;
    int t = m % TT;
    int mbase = m - t;
    float acc = cb[h];
#pragma unroll
    for (int k = 0; k < 4; k++) {
        int tt = t + k - 3;
        if (tt >= 0)
            acc += cw[h * 4 + k] * g_u[(size_t)(mbase + tt) * GG + HH + h];
    }
    g_xc[id] = acc;
    __nv_bfloat16 hi, lo;
    split1(acc, hi, lo);
    g_ahi[id] = hi;
    g_alo[id] = lo;
}

// ---------------- gate math: coalesced float2 in/out ----------------
__global__ __launch_bounds__(256) void gate_kernel(const float* __restrict__ b_gates)
{
    int id = blockIdx.x * blockDim.x + threadIdx.x;
    if (id >= MM * HH) return;
    int h = id % HH;
    int m = id / HH;
    float2 fi = ((const float2*)(g_gp + (size_t)m * GG))[h];   // (forget, inp)
    float f  = fi.x + b_gates[h];
    float iv = fi.y + b_gates[HH + h];
    float sf = 1.f / (1.f + expf(-f));
    float alpha = expf(-8.f * g_sp[h] * sf);
    float beta  = sqrtf(1.f - alpha * alpha + 1e-6f);
    float si = 1.f / (1.f + expf(-iv));
    float xs = beta * si * g_xc[id];
    g_axs[id] = make_float2(alpha, xs);
}

// ---------------- chunked scan (recompute form, float2 alpha/xs) ----------------
__global__ __launch_bounds__(256) void scan1_kernel()
{
    int id = blockIdx.x * blockDim.x + threadIdx.x;
    if (id >= NB * NCHUNK * HH) return;
    int h = id % HH;
    int r = id / HH;
    int c = r % NCHUNK;
    int n = r / NCHUNK;
    float arun = 1.f, hrun = 0.f;
    size_t base = ((size_t)n * TT + c * CLEN) * HH + h;
#pragma unroll 4
    for (int tl = 0; tl < CLEN; tl++) {
        float2 ax = g_axs[base + (size_t)tl * HH];
        hrun = ax.x * hrun + ax.y;
        arun *= ax.x;
    }
    g_carryA[id] = arun;
    g_carryH[id] = hrun;
}
__global__ __launch_bounds__(256) void scan2_kernel()
{
    int id = blockIdx.x * blockDim.x + threadIdx.x;
    if (id >= NB * HH) return;
    int h = id % HH;
    int n = id / HH;
    float hin = 0.f;
    for (int c = 0; c < NCHUNK; c++) {
        int j = (n * NCHUNK + c) * HH + h;
        g_chunkIn[j] = hin;
        hin = g_carryA[j] * hin + g_carryH[j];
    }
}
__global__ __launch_bounds__(256) void scan3_kernel()
{
    int id = blockIdx.x * blockDim.x + threadIdx.x;
    if (id >= NB * NCHUNK * HH) return;
    int h = id % HH;
    int r = id / HH;
    int c = r % NCHUNK;
    int n = r / NCHUNK;
    float hrun = g_chunkIn[(n * NCHUNK + c) * HH + h];
    size_t m0 = (size_t)n * TT + c * CLEN;
#pragma unroll 4
    for (int tl = 0; tl < CLEN; tl++) {
        size_t m = m0 + tl;
        size_t idx = m * HH + h;
        float2 ax = g_axs[idx];
        hrun = ax.x * hrun + ax.y;
        float gate = g_u[m * GG + h];
        float ge = 0.5f * gate * (1.f + erff(gate * 0.70710678118654752f));
        float v = ge * hrun;
        __nv_bfloat16 hi, lo;
        split1(v, hi, lo);
        g_ahi[idx] = hi;
        g_alo[idx] = lo;
    }
}

// ---------------- launch ----------------
extern "C" void kernel_launch(void* const* d_in, const int* in_sizes, int n_in,
                              void* d_out, int out_size)
{
    const float* x          = (const float*)d_in[0];
    const float* W_in       = (const float*)d_in[1];
    const float* conv_w     = (const float*)d_in[2];
    const float* conv_b     = (const float*)d_in[3];
    const float* W_gates    = (const float*)d_in[4];
    const float* b_gates    = (const float*)d_in[5];
    const float* forget_b   = (const float*)d_in[6];
    const float* W_out      = (const float*)d_in[7];
    float* out = (float*)d_out;

    // 1) splits + softplus precompute
    split_x<<<(MM * DD / 4 + 255) / 256, 256>>>(x, MM * DD / 4);
    split_w<<<(GG * DD / 4 + 255) / 256, 256>>>(W_in, GG * DD / 4);
    prep_sp<<<(HH + 255) / 256, 256>>>(forget_b);
    // 2) u = x @ W_in^T
    {
        dim3 grid(GG / BN, MM / BM);
        tcgemm_in<<<grid, 256>>>();
    }
    // 3) causal conv
    conv_kernel<<<(MM * HH) / 256, 256>>>(conv_w, conv_b);
    split_w_gates<<<(GG * HH / 4 + 255) / 256, 256>>>(W_gates, GG * HH / 4);
    // 4) gates GEMM (permuted pairs) then coalesced gate math -> (alpha, xs)
    {
        dim3 grid(GG / BN, MM / BM);
        tcgemm_gates<<<grid, 256>>>();
    }
    gate_kernel<<<(MM * HH) / 256, 256>>>(b_gates);
    // 5) chunked scan (carries -> combine -> recompute+gelu+split)
    scan1_kernel<<<(NB * NCHUNK * HH) / 256, 256>>>();
    scan2_kernel<<<(NB * HH + 255) / 256, 256>>>();
    scan3_kernel<<<(NB * NCHUNK * HH) / 256, 256>>>();
    split_w<<<(DD * HH / 4 + 255) / 256, 256>>>(W_out, DD * HH / 4);
    // 6) out = ga @ W_out^T
    {
        dim3 grid(DD / BN, MM / BM);
        tcgemm_out<<<grid, 256>>>(out);
    }
}

// round 13
// speedup vs baseline: 1.3313x; 1.3313x over previous
#include <cuda_runtime.h>
#include <cuda_bf16.h>
#include <math.h>
#include <stdint.h>

// ---------------- problem dims ----------------
#define NB 8
#define TT 2048
#define DD 1024
#define HH 1536
#define GG 3072              // 2*H
#define MM (NB*TT)           // 16384
#define NCHUNK 16
#define CLEN (TT/NCHUNK)     // 128

// ---------------- scratch ----------------
__device__ float g_u[(size_t)MM*GG];        // u = x @ W_in^T  (gate | xh)
__device__ float g_xc[(size_t)MM*HH];       // conv output fp32
__device__ float g_gp[(size_t)MM*GG];       // gates GEMM out, permuted pairs (forget,inp)
__device__ float2 g_axs[(size_t)MM*HH];     // interleaved (alpha, xs)
__device__ float g_sp[HH];                  // softplus(forget_base)
__device__ float g_carryA[NB*NCHUNK*HH];
__device__ float g_carryH[NB*NCHUNK*HH];
__device__ float g_chunkIn[NB*NCHUNK*HH];
// split-bf16 operand buffers
__device__ __nv_bfloat16 g_ahi[(size_t)MM*HH];
__device__ __nv_bfloat16 g_alo[(size_t)MM*HH];
__device__ __nv_bfloat16 g_bhi[(size_t)GG*HH];
__device__ __nv_bfloat16 g_blo[(size_t)GG*HH];

// ---------------- PTX helpers ----------------
__device__ __forceinline__ uint32_t smem_u32(const void* p) {
    uint32_t a;
    asm("{ .reg .u64 t; cvta.to.shared.u64 t, %1; cvt.u32.u64 %0, t; }" : "=r"(a) : "l"(p));
    return a;
}
__device__ __forceinline__ void ldsm_x4(uint32_t& r0, uint32_t& r1, uint32_t& r2, uint32_t& r3,
                                        uint32_t addr) {
    asm volatile("ldmatrix.sync.aligned.m8n8.x4.shared.b16 {%0,%1,%2,%3}, [%4];"
                 : "=r"(r0), "=r"(r1), "=r"(r2), "=r"(r3) : "r"(addr));
}
__device__ __forceinline__ void mma16816(float* c,
                                         uint32_t a0, uint32_t a1, uint32_t a2, uint32_t a3,
                                         uint32_t b0, uint32_t b1) {
    asm volatile(
        "mma.sync.aligned.m16n8k16.row.col.f32.bf16.bf16.f32 "
        "{%0,%1,%2,%3}, {%4,%5,%6,%7}, {%8,%9}, {%0,%1,%2,%3};"
        : "+f"(c[0]), "+f"(c[1]), "+f"(c[2]), "+f"(c[3])
        : "r"(a0), "r"(a1), "r"(a2), "r"(a3), "r"(b0), "r"(b1));
}

// ---------------- split-bf16 TN GEMM via mma.sync (R10-proven, UNCHANGED) ------
// C[M,N] = (Ahi+Alo)[M,K] * (Bhi+Blo)[N,K]^T; 3 terms: hi*hi + hi*lo + lo*hi
// block 128x128, BK=32, 256 threads = 8 warps (2 M x 4 N), warp tile 64x32
// register prefetch + double-buffered smem (1 sync per chunk)
#define BM 128
#define BN 128
#define BK 32
#define SSTR 40                 // smem row stride in bf16 (32 + 8 pad)

__device__ __forceinline__ void tn_gemm_body(
    const __nv_bfloat16* __restrict__ Ahi, const __nv_bfloat16* __restrict__ Alo,
    const __nv_bfloat16* __restrict__ Bhi, const __nv_bfloat16* __restrict__ Blo,
    const float* __restrict__ bias, float* __restrict__ C,
    int Ndim, int Kdim)
{
    __shared__ __align__(16) __nv_bfloat16 sA[2][BM * SSTR];
    __shared__ __align__(16) __nv_bfloat16 sB[2][BN * SSTR];

    const int tid = threadIdx.x;
    const int wid = tid >> 5;
    const int lane = tid & 31;
    const int warp_m = wid >> 2;       // 0..1
    const int warp_n = wid & 3;        // 0..3
    const int m0 = blockIdx.y * BM;
    const int n0 = blockIdx.x * BN;

    const int r0i = tid >> 2, q0 = tid & 3;
    const int r1i = (tid + 256) >> 2;

    float acc[4][4][4];
#pragma unroll
    for (int i = 0; i < 4; i++)
#pragma unroll
        for (int j = 0; j < 4; j++)
#pragma unroll
            for (int v = 0; v < 4; v++) acc[i][j][v] = 0.f;

    const int kcs = Kdim / BK;
    const int nch = 3 * kcs;

    uint4 ra0, ra1, rb0, rb1;
    auto fetch = [&](int ch) {
        const int seg = ch / kcs;
        const int kc = ch - seg * kcs;
        const __nv_bfloat16* Ap = (seg < 2) ? Ahi : Alo;
        const __nv_bfloat16* Bp = (seg == 1) ? Blo : Bhi;
        const __nv_bfloat16* ab = Ap + (size_t)m0 * Kdim + kc * BK;
        const __nv_bfloat16* bb = Bp + (size_t)n0 * Kdim + kc * BK;
        ra0 = *(const uint4*)(ab + (size_t)r0i * Kdim + q0 * 8);
        ra1 = *(const uint4*)(ab + (size_t)r1i * Kdim + q0 * 8);
        rb0 = *(const uint4*)(bb + (size_t)r0i * Kdim + q0 * 8);
        rb1 = *(const uint4*)(bb + (size_t)r1i * Kdim + q0 * 8);
    };
    auto stage = [&](int s) {
        *(uint4*)(sA[s] + r0i * SSTR + q0 * 8) = ra0;
        *(uint4*)(sA[s] + r1i * SSTR + q0 * 8) = ra1;
        *(uint4*)(sB[s] + r0i * SSTR + q0 * 8) = rb0;
        *(uint4*)(sB[s] + r1i * SSTR + q0 * 8) = rb1;
    };

    fetch(0);
    stage(0);
    __syncthreads();

    for (int ch = 0; ch < nch; ch++) {
        const int cur = ch & 1;
        const bool more = (ch + 1 < nch);
        if (more) fetch(ch + 1);

        const uint32_t sAu = smem_u32(sA[cur]);
        const uint32_t sBu = smem_u32(sB[cur]);
#pragma unroll
        for (int kk = 0; kk < 2; kk++) {
            uint32_t a[4][4];
#pragma unroll
            for (int mi = 0; mi < 4; mi++) {
                uint32_t addr = sAu +
                    (uint32_t)(((warp_m * 64 + mi * 16 + (lane & 15)) * SSTR
                                + kk * 16 + (lane >> 4) * 8) * 2);
                ldsm_x4(a[mi][0], a[mi][1], a[mi][2], a[mi][3], addr);
            }
            uint32_t br[2][4];
#pragma unroll
            for (int nb = 0; nb < 2; nb++) {
                uint32_t addr = sBu +
                    (uint32_t)(((warp_n * 32 + nb * 16 + (lane & 15)) * SSTR
                                + kk * 16 + (lane >> 4) * 8) * 2);
                ldsm_x4(br[nb][0], br[nb][1], br[nb][2], br[nb][3], addr);
            }
#pragma unroll
            for (int mi = 0; mi < 4; mi++) {
#pragma unroll
                for (int nb = 0; nb < 2; nb++) {
                    mma16816(acc[mi][nb * 2 + 0], a[mi][0], a[mi][1], a[mi][2], a[mi][3],
                             br[nb][0], br[nb][2]);
                    mma16816(acc[mi][nb * 2 + 1], a[mi][0], a[mi][1], a[mi][2], a[mi][3],
                             br[nb][1], br[nb][3]);
                }
            }
        }

        if (more) {
            stage(cur ^ 1);
            __syncthreads();
        }
    }

    // ---- epilogue: plain coalesced store ----
    const int crow0 = m0 + warp_m * 64 + (lane >> 2);
    const int ccol0 = n0 + warp_n * 32 + (lane & 3) * 2;
#pragma unroll
    for (int mi = 0; mi < 4; mi++) {
#pragma unroll
        for (int ni = 0; ni < 4; ni++) {
            int row = crow0 + mi * 16;
            int col = ccol0 + ni * 8;
            float b0 = 0.f, b1 = 0.f;
            if (bias) { b0 = bias[col]; b1 = bias[col + 1]; }
            float2 v0, v1;
            v0.x = acc[mi][ni][0] + b0; v0.y = acc[mi][ni][1] + b1;
            v1.x = acc[mi][ni][2] + b0; v1.y = acc[mi][ni][3] + b1;
            *(float2*)(C + (size_t)row * Ndim + col)       = v0;
            *(float2*)(C + (size_t)(row + 8) * Ndim + col) = v1;
        }
    }
}

__global__ __launch_bounds__(256, 2) void tcgemm_in()
{
    tn_gemm_body(g_ahi, g_alo, g_bhi, g_blo, nullptr, g_u, GG, DD);
}
__global__ __launch_bounds__(256, 2) void tcgemm_gates()
{
    tn_gemm_body(g_ahi, g_alo, g_bhi, g_blo, nullptr, g_gp, GG, HH);
}
__global__ __launch_bounds__(256, 2) void tcgemm_out(float* __restrict__ out)
{
    tn_gemm_body(g_ahi, g_alo, g_bhi, g_blo, nullptr, out, DD, HH);
}

// ---------------- fp32 -> (hi, lo) bf16 split ----------------
__device__ __forceinline__ void split1(float v, __nv_bfloat16& hi, __nv_bfloat16& lo) {
    __nv_bfloat16 h = __float2bfloat16(v);
    hi = h;
    lo = __float2bfloat16(v - __bfloat162float(h));
}
__global__ __launch_bounds__(256) void split_x(const float* __restrict__ x, int n4)
{
    int id = blockIdx.x * blockDim.x + threadIdx.x;
    if (id >= n4) return;
    float4 v = ((const float4*)x)[id];
    __nv_bfloat16 h0, h1, h2, h3, l0, l1, l2, l3;
    split1(v.x, h0, l0); split1(v.y, h1, l1);
    split1(v.z, h2, l2); split1(v.w, h3, l3);
    ((__nv_bfloat162*)g_ahi)[id * 2 + 0] = __nv_bfloat162(h0, h1);
    ((__nv_bfloat162*)g_ahi)[id * 2 + 1] = __nv_bfloat162(h2, h3);
    ((__nv_bfloat162*)g_alo)[id * 2 + 0] = __nv_bfloat162(l0, l1);
    ((__nv_bfloat162*)g_alo)[id * 2 + 1] = __nv_bfloat162(l2, l3);
}
__global__ __launch_bounds__(256) void split_w(const float* __restrict__ w, int n4)
{
    int id = blockIdx.x * blockDim.x + threadIdx.x;
    if (id >= n4) return;
    float4 v = ((const float4*)w)[id];
    __nv_bfloat16 h0, h1, h2, h3, l0, l1, l2, l3;
    split1(v.x, h0, l0); split1(v.y, h1, l1);
    split1(v.z, h2, l2); split1(v.w, h3, l3);
    ((__nv_bfloat162*)g_bhi)[id * 2 + 0] = __nv_bfloat162(h0, h1);
    ((__nv_bfloat162*)g_bhi)[id * 2 + 1] = __nv_bfloat162(h2, h3);
    ((__nv_bfloat162*)g_blo)[id * 2 + 0] = __nv_bfloat162(l0, l1);
    ((__nv_bfloat162*)g_blo)[id * 2 + 1] = __nv_bfloat162(l2, l3);
}
// permuted split for W_gates: dst row 2h = W_gates row h (forget), 2h+1 = row HH+h (inp)
__global__ __launch_bounds__(256) void split_w_gates(const float* __restrict__ w, int n4)
{
    int id = blockIdx.x * blockDim.x + threadIdx.x;
    if (id >= n4) return;
    int e = id * 4;
    int j = e / HH;                    // dst row
    int o = e - j * HH;
    int src = (j & 1) ? (HH + (j >> 1)) : (j >> 1);
    float4 v = *(const float4*)(w + (size_t)src * HH + o);
    __nv_bfloat16 h0, h1, h2, h3, l0, l1, l2, l3;
    split1(v.x, h0, l0); split1(v.y, h1, l1);
    split1(v.z, h2, l2); split1(v.w, h3, l3);
    ((__nv_bfloat162*)g_bhi)[id * 2 + 0] = __nv_bfloat162(h0, h1);
    ((__nv_bfloat162*)g_bhi)[id * 2 + 1] = __nv_bfloat162(h2, h3);
    ((__nv_bfloat162*)g_blo)[id * 2 + 0] = __nv_bfloat162(l0, l1);
    ((__nv_bfloat162*)g_blo)[id * 2 + 1] = __nv_bfloat162(l2, l3);
}
__global__ __launch_bounds__(256) void prep_sp(const float* __restrict__ fb)
{
    int i = blockIdx.x * blockDim.x + threadIdx.x;
    if (i < HH) g_sp[i] = log1pf(expf(fb[i]));
}

// ---------------- causal depthwise conv: 4 timesteps/thread, fused split -------
__global__ __launch_bounds__(256) void conv4_kernel(
    const float* __restrict__ cw, const float* __restrict__ cb)
{
    int id = blockIdx.x * blockDim.x + threadIdx.x;
    if (id >= (MM / 4) * HH) return;
    int h = id % HH;
    int g = id / HH;                   // 0 .. MM/4-1
    int tq = g % (TT / 4);
    int n  = g / (TT / 4);
    int t0 = tq * 4;
    const size_t mrow = (size_t)n * TT;

    float w0 = cw[h * 4 + 0], w1 = cw[h * 4 + 1];
    float w2 = cw[h * 4 + 2], w3 = cw[h * 4 + 3];
    float bb = cb[h];

    float xv[7];
#pragma unroll
    for (int j = 0; j < 7; j++) {
        int t = t0 - 3 + j;
        xv[j] = (t >= 0) ? g_u[(mrow + t) * GG + HH + h] : 0.f;
    }
#pragma unroll
    for (int i = 0; i < 4; i++) {
        float acc = bb + w0 * xv[i] + w1 * xv[i + 1] + w2 * xv[i + 2] + w3 * xv[i + 3];
        size_t idx = (mrow + t0 + i) * HH + h;
        g_xc[idx] = acc;
        __nv_bfloat16 hi, lo;
        split1(acc, hi, lo);
        g_ahi[idx] = hi;
        g_alo[idx] = lo;
    }
}

// ---------------- scan pass 1 with FUSED gate math ----------------
// computes alpha/xs from g_gp (+bias) + g_xc, writes g_axs, accumulates carries
__global__ __launch_bounds__(256) void scan1_gate_kernel(const float* __restrict__ b_gates)
{
    int id = blockIdx.x * blockDim.x + threadIdx.x;
    if (id >= NB * NCHUNK * HH) return;
    int h = id % HH;
    int r = id / HH;
    int c = r % NCHUNK;
    int n = r / NCHUNK;

    const float bf_ = b_gates[h];
    const float bi_ = b_gates[HH + h];
    const float sp8 = -8.f * g_sp[h];

    float arun = 1.f, hrun = 0.f;
    size_t m0 = (size_t)n * TT + c * CLEN;
#pragma unroll 2
    for (int tl = 0; tl < CLEN; tl++) {
        size_t m = m0 + tl;
        float2 fi = ((const float2*)(g_gp + m * GG))[h];   // (forget, inp)
        float f  = fi.x + bf_;
        float iv = fi.y + bi_;
        float sf = 1.f / (1.f + expf(-f));
        float alpha = expf(sp8 * sf);
        float beta  = sqrtf(1.f - alpha * alpha + 1e-6f);
        float si = 1.f / (1.f + expf(-iv));
        size_t idx = m * HH + h;
        float xs = beta * si * g_xc[idx];
        g_axs[idx] = make_float2(alpha, xs);
        hrun = alpha * hrun + xs;
        arun *= alpha;
    }
    g_carryA[id] = arun;
    g_carryH[id] = hrun;
}
__global__ __launch_bounds__(256) void scan2_kernel()
{
    int id = blockIdx.x * blockDim.x + threadIdx.x;
    if (id >= NB * HH) return;
    int h = id % HH;
    int n = id / HH;
    float hin = 0.f;
    for (int c = 0; c < NCHUNK; c++) {
        int j = (n * NCHUNK + c) * HH + h;
        g_chunkIn[j] = hin;
        hin = g_carryA[j] * hin + g_carryH[j];
    }
}
__global__ __launch_bounds__(256) void scan3_kernel()
{
    int id = blockIdx.x * blockDim.x + threadIdx.x;
    if (id >= NB * NCHUNK * HH) return;
    int h = id % HH;
    int r = id / HH;
    int c = r % NCHUNK;
    int n = r / NCHUNK;
    float hrun = g_chunkIn[(n * NCHUNK + c) * HH + h];
    size_t m0 = (size_t)n * TT + c * CLEN;
#pragma unroll 4
    for (int tl = 0; tl < CLEN; tl++) {
        size_t m = m0 + tl;
        size_t idx = m * HH + h;
        float2 ax = g_axs[idx];
        hrun = ax.x * hrun + ax.y;
        float gate = g_u[m * GG + h];
        float ge = 0.5f * gate * (1.f + erff(gate * 0.70710678118654752f));
        float v = ge * hrun;
        __nv_bfloat16 hi, lo;
        split1(v, hi, lo);
        g_ahi[idx] = hi;
        g_alo[idx] = lo;
    }
}

// ---------------- launch ----------------
extern "C" void kernel_launch(void* const* d_in, const int* in_sizes, int n_in,
                              void* d_out, int out_size)
{
    const float* x          = (const float*)d_in[0];
    const float* W_in       = (const float*)d_in[1];
    const float* conv_w     = (const float*)d_in[2];
    const float* conv_b     = (const float*)d_in[3];
    const float* W_gates    = (const float*)d_in[4];
    const float* b_gates    = (const float*)d_in[5];
    const float* forget_b   = (const float*)d_in[6];
    const float* W_out      = (const float*)d_in[7];
    float* out = (float*)d_out;

    // 1) splits + softplus precompute
    split_x<<<(MM * DD / 4 + 255) / 256, 256>>>(x, MM * DD / 4);
    split_w<<<(GG * DD / 4 + 255) / 256, 256>>>(W_in, GG * DD / 4);
    prep_sp<<<(HH + 255) / 256, 256>>>(forget_b);
    // 2) u = x @ W_in^T
    {
        dim3 grid(GG / BN, MM / BM);
        tcgemm_in<<<grid, 256>>>();
    }
    // 3) causal conv (4 timesteps per thread)
    conv4_kernel<<<((MM / 4) * HH + 255) / 256, 256>>>(conv_w, conv_b);
    split_w_gates<<<(GG * HH / 4 + 255) / 256, 256>>>(W_gates, GG * HH / 4);
    // 4) gates GEMM (permuted pairs)
    {
        dim3 grid(GG / BN, MM / BM);
        tcgemm_gates<<<grid, 256>>>();
    }
    // 5) chunked scan: pass1 fuses gate math; combine; recompute+gelu+split
    scan1_gate_kernel<<<(NB * NCHUNK * HH) / 256, 256>>>(b_gates);
    scan2_kernel<<<(NB * HH + 255) / 256, 256>>>();
    scan3_kernel<<<(NB * NCHUNK * HH) / 256, 256>>>();
    split_w<<<(DD * HH / 4 + 255) / 256, 256>>>(W_out, DD * HH / 4);
    // 6) out = ga @ W_out^T
    {
        dim3 grid(DD / BN, MM / BM);
        tcgemm_out<<<grid, 256>>>(out);
    }
}